// round 13
// baseline (speedup 1.0000x reference)
#include <cuda_runtime.h>
#include <cuda_fp16.h>
#include <cstdint>

// ---------------- buffers ----------------
__device__ __half g_Wh[128 * 256];            // W_tree fp16
__device__ __half g_embh[100000ull * 128ull]; // embedding fp16
__device__ int    g_tok_is64;

// ---------------- prep (single launch) ----------------
__global__ void prep_all(const float* __restrict__ emb, const float* __restrict__ W,
                         const int* __restrict__ tok32) {
    if (blockIdx.x == 0) {
        __shared__ int bad;
        if (threadIdx.x == 0) bad = 0;
        __syncthreads();
        if (threadIdx.x < 128 && tok32[2 * threadIdx.x + 1] != 0) atomicAdd(&bad, 1);
        __syncthreads();
        if (threadIdx.x == 0) g_tok_is64 = (bad == 0);
        for (int i = threadIdx.x; i < 128 * 256; i += 256)
            g_Wh[i] = __float2half_rn(W[i]);
    }
    const float4* src = (const float4*)emb;
    uint2* dst = (uint2*)g_embh;
    const int n4 = 100000 * 32;
    for (int i = blockIdx.x * blockDim.x + threadIdx.x; i < n4;
         i += gridDim.x * blockDim.x) {
        float4 v = src[i];
        __half2 h0 = __floats2half2_rn(v.x, v.y);
        __half2 h1 = __floats2half2_rn(v.z, v.w);
        uint2 o;
        o.x = *(uint32_t*)&h0;
        o.y = *(uint32_t*)&h1;
        dst[i] = o;
    }
}

// ---------------- helpers ----------------
__device__ __forceinline__ float tanh_fast(float x) {
    float t;
    asm("ex2.approx.f32 %0, %1;" : "=f"(t) : "f"(x * 2.885390082f));
    return __fdividef(t - 1.f, t + 1.f);
}

__device__ __forceinline__ uint32_t packh2(float lo, float hi) {
    __half2 h = __floats2half2_rn(lo, hi);
    return *(uint32_t*)&h;
}

__device__ __forceinline__ void cp16(uint32_t dst, const void* src) {
    asm volatile("cp.async.cg.shared.global [%0], [%1], 16;" :: "r"(dst), "l"(src));
}

__device__ __forceinline__ void ldsm4(uint32_t addr, uint32_t* r) {
    asm volatile("ldmatrix.sync.aligned.m8n8.x4.shared.b16 {%0,%1,%2,%3}, [%4];"
                 : "=r"(r[0]), "=r"(r[1]), "=r"(r[2]), "=r"(r[3]) : "r"(addr));
}

__device__ __forceinline__ void mma_f16(float* d, const uint32_t* a,
                                        uint32_t b0, uint32_t b1) {
    asm volatile(
        "mma.sync.aligned.m16n8k16.row.col.f32.f16.f16.f32 "
        "{%0,%1,%2,%3},{%4,%5,%6,%7},{%8,%9},{%0,%1,%2,%3};"
        : "+f"(d[0]), "+f"(d[1]), "+f"(d[2]), "+f"(d[3])
        : "r"(a[0]), "r"(a[1]), "r"(a[2]), "r"(a[3]), "r"(b0), "r"(b1));
}

__device__ __forceinline__ void sts32(uint32_t addr, uint32_t v) {
    asm volatile("st.shared.b32 [%0], %1;" :: "r"(addr), "r"(v));
}

// smem layout (99840 B, 2 CTAs/SM):
//  [0,32K)   workspace: A stages (2x16K) -> INT1[64,256] 32K -> INT2[32,256] 16K
//            -> INT5[4,256] 2K / INT6[2,256] @4K / roots fp32 @8K
//  [16K,24K) INT3[16,256], [24K,28K) INT4[8,256]
//  [32K,96K) B resident (4 chunks x 16K); bias @98304, tok @98816
#define FB_OFF  32768u
#define FBIAS   98304u
#define FTOK    98816u
#define F_SMEM  99840u

__global__ __launch_bounds__(256, 2)
void tree_mono(const void* __restrict__ tokens, const float* __restrict__ bias,
               const float* __restrict__ Wc, const float* __restrict__ bc,
               float* __restrict__ out3)
{
    extern __shared__ char smem[];
    const uint32_t sb = (uint32_t)__cvta_generic_to_shared(smem);
    float* bias_s = (float*)(smem + FBIAS);
    int*   tok_s  = (int*)(smem + FTOK);

    const int tid = threadIdx.x, lane = tid & 31, warp = tid >> 5;
    const int m0p = blockIdx.x * 128;
    const int jj = lane >> 3, rr = lane & 7;
    const int frow = (jj & 1) * 8 + rr;   // ldsm lane row (A and B — proven pair)
    const int fku  = jj >> 1;             // ldsm k-unit select
    const int q = lane >> 2, tg = lane & 3;

    if (tid < 128) bias_s[tid] = bias[tid];
    {
        const int is64 = g_tok_is64;
        int r = tid >> 1, side = tid & 1;
        int g = m0p + r;
        long long ti = (long long)(g >> 6) * 128 + 2 * (g & 63) + side;
        tok_s[tid] = is64 ? (int)((const long long*)tokens)[ti]
                          : ((const int*)tokens)[ti];
    }
    __syncthreads();

    uint32_t ko[4];
#pragma unroll
    for (int ks = 0; ks < 4; ++ks)
        ko[ks] = (uint32_t)((((ks * 2 + fku) ^ rr) << 4));

    // chunked emit: pair (r,c),(r,c+1) of a phase output feeding an [Mh,256]
    // next-level input; chb = Mh*128 bytes per chunk
    auto emit_h = [&](uint32_t base, uint32_t chb, int r, int c, float v0, float v1) {
        uint32_t h2 = packh2(tanh_fast(v0 + bias_s[c]), tanh_fast(v1 + bias_s[c + 1]));
        int R = r >> 1, c2 = ((r & 1) << 7) + c;
        int ch = c2 >> 6, kk = c2 & 63;
        sts32(sb + base + (uint32_t)ch * chb + (uint32_t)(R * 128 +
              (((kk >> 3) ^ (R & 7)) << 4) + ((kk & 7) << 1)), h2);
    };

    // ================= phase 0: level-0, M=128, gather, warp 32x64 ============
    uint32_t adst[4];
    int aL[4], aR[4], uo[4];
#pragma unroll
    for (int p = 0; p < 4; ++p) {
        int idx = tid + p * 256;
        int row = idx >> 3, u = idx & 7;
        adst[p] = (uint32_t)(row * 128 + ((u ^ (row & 7)) << 4));
        aL[p] = tok_s[2 * row]; aR[p] = tok_s[2 * row + 1]; uo[p] = u * 8;
    }
    auto issueA = [&](int kc) {
        const uint32_t d = sb + (uint32_t)(kc & 1) * 16384u;
#pragma unroll
        for (int p = 0; p < 4; ++p) {
            long long tk = (kc >> 1) ? aR[p] : aL[p];
            cp16(d + adst[p], g_embh + tk * 128 + (kc & 1) * 64 + uo[p]);
        }
    };
    uint32_t bdst[4];
    const __half* bptr[4];
#pragma unroll
    for (int p = 0; p < 4; ++p) {
        int i = tid + p * 256;
        int row = i >> 3, u = i & 7;
        bdst[p] = (uint32_t)(row * 128 + ((u ^ (row & 7)) << 4));
        bptr[p] = g_Wh + row * 256 + u * 8;
    }
    auto issueB = [&](int ch) {
        const uint32_t d = sb + FB_OFF + (uint32_t)ch * 16384u;
#pragma unroll
        for (int p = 0; p < 4; ++p) cp16(d + bdst[p], bptr[p] + ch * 64);
    };

    issueB(0); issueA(0); asm volatile("cp.async.commit_group;");
    issueB(1); issueA(1); asm volatile("cp.async.commit_group;");
    issueB(2); asm volatile("cp.async.commit_group;");
    issueB(3); asm volatile("cp.async.commit_group;");

    const int wm1 = (warp & 3) * 32, wn1 = (warp >> 2) * 64;
    uint32_t am1[2], bn1[4];
#pragma unroll
    for (int i = 0; i < 2; ++i) am1[i] = (uint32_t)((wm1 + i * 16 + frow) * 128);
#pragma unroll
    for (int i = 0; i < 4; ++i) bn1[i] = (uint32_t)((wn1 + i * 16 + frow) * 128);

    float acc[2][8][4];
#pragma unroll
    for (int a = 0; a < 2; ++a)
#pragma unroll
        for (int b = 0; b < 8; ++b)
#pragma unroll
            for (int c = 0; c < 4; ++c) acc[a][b][c] = 0.f;

    for (int kc = 0; kc < 4; ++kc) {
        if (kc < 2)       asm volatile("cp.async.wait_group 3;");
        else if (kc == 2) asm volatile("cp.async.wait_group 1;");
        else              asm volatile("cp.async.wait_group 0;");
        __syncthreads();
        const uint32_t Ab = sb + (uint32_t)(kc & 1) * 16384u;
        const uint32_t Bb = sb + FB_OFF + (uint32_t)kc * 16384u;
#pragma unroll
        for (int ks = 0; ks < 4; ++ks) {
            uint32_t af[2][4], bf[4][4];
#pragma unroll
            for (int mi = 0; mi < 2; ++mi) ldsm4(Ab + am1[mi] + ko[ks], af[mi]);
#pragma unroll
            for (int nt = 0; nt < 4; ++nt) ldsm4(Bb + bn1[nt] + ko[ks], bf[nt]);
#pragma unroll
            for (int ni = 0; ni < 8; ++ni) {
                uint32_t b0 = bf[ni >> 1][ni & 1];
                uint32_t b1 = bf[ni >> 1][2 + (ni & 1)];
#pragma unroll
                for (int mi = 0; mi < 2; ++mi) mma_f16(acc[mi][ni], af[mi], b0, b1);
            }
        }
        __syncthreads();
        if (kc < 2) { issueA(kc + 2); asm volatile("cp.async.commit_group;"); }
    }

    // emit -> INT1 [64,256] @0, chunks 8K
#pragma unroll
    for (int mi = 0; mi < 2; ++mi)
#pragma unroll
        for (int ni = 0; ni < 8; ++ni) {
            int col = wn1 + ni * 8 + 2 * tg;
            int r0 = wm1 + mi * 16 + q;
            emit_h(0u, 8192u, r0,     col, acc[mi][ni][0], acc[mi][ni][1]);
            emit_h(0u, 8192u, r0 + 8, col, acc[mi][ni][2], acc[mi][ni][3]);
        }
    __syncthreads();

    // ================= phase 1: level-1, M=64, warp 16x64 =====================
    {
        const int wm = (warp & 3) * 16, wn = (warp >> 2) * 64;
        const uint32_t am = (uint32_t)((wm + frow) * 128);
        uint32_t bn[4];
#pragma unroll
        for (int i = 0; i < 4; ++i) bn[i] = (uint32_t)((wn + i * 16 + frow) * 128);

        float ac[8][4];
#pragma unroll
        for (int b = 0; b < 8; ++b)
#pragma unroll
            for (int c = 0; c < 4; ++c) ac[b][c] = 0.f;

#pragma unroll
        for (int kc = 0; kc < 4; ++kc) {
            const uint32_t Ab = sb + (uint32_t)kc * 8192u;
            const uint32_t Bb = sb + FB_OFF + (uint32_t)kc * 16384u;
#pragma unroll
            for (int ks = 0; ks < 4; ++ks) {
                uint32_t af[4], bf[4][4];
                ldsm4(Ab + am + ko[ks], af);
#pragma unroll
                for (int nt = 0; nt < 4; ++nt) ldsm4(Bb + bn[nt] + ko[ks], bf[nt]);
#pragma unroll
                for (int ni = 0; ni < 8; ++ni)
                    mma_f16(ac[ni], af, bf[ni >> 1][ni & 1], bf[ni >> 1][2 + (ni & 1)]);
            }
        }
        __syncthreads();   // all INT1 reads done -> overlay INT2
#pragma unroll
        for (int ni = 0; ni < 8; ++ni) {
            int col = wn + ni * 8 + 2 * tg;
            int r0 = wm + q;
            emit_h(0u, 4096u, r0,     col, ac[ni][0], ac[ni][1]);
            emit_h(0u, 4096u, r0 + 8, col, ac[ni][2], ac[ni][3]);
        }
        __syncthreads();
    }

    // ================= phase 2: level-2, M=32, warp 16x32 =====================
    {
        const int wm = (warp & 1) * 16, wn = (warp >> 1) * 32;
        const uint32_t am = (uint32_t)((wm + frow) * 128);
        uint32_t bn[2];
#pragma unroll
        for (int i = 0; i < 2; ++i) bn[i] = (uint32_t)((wn + i * 16 + frow) * 128);

        float ac[4][4];
#pragma unroll
        for (int b = 0; b < 4; ++b)
#pragma unroll
            for (int c = 0; c < 4; ++c) ac[b][c] = 0.f;

#pragma unroll
        for (int kc = 0; kc < 4; ++kc) {
            const uint32_t Ab = sb + (uint32_t)kc * 4096u;
            const uint32_t Bb = sb + FB_OFF + (uint32_t)kc * 16384u;
#pragma unroll
            for (int ks = 0; ks < 4; ++ks) {
                uint32_t af[4], bf[2][4];
                ldsm4(Ab + am + ko[ks], af);
#pragma unroll
                for (int nt = 0; nt < 2; ++nt) ldsm4(Bb + bn[nt] + ko[ks], bf[nt]);
#pragma unroll
                for (int ni = 0; ni < 4; ++ni)
                    mma_f16(ac[ni], af, bf[ni >> 1][ni & 1], bf[ni >> 1][2 + (ni & 1)]);
            }
        }
        // writes [16K,24K), reads [0,16K): disjoint
#pragma unroll
        for (int ni = 0; ni < 4; ++ni) {
            int col = wn + ni * 8 + 2 * tg;
            int r0 = wm + q;
            emit_h(16384u, 2048u, r0,     col, ac[ni][0], ac[ni][1]);
            emit_h(16384u, 2048u, r0 + 8, col, ac[ni][2], ac[ni][3]);
        }
        __syncthreads();
    }

    // ====== phases 3-6: single m16 A-tile, 8 warps x n16; M = 16,8,4,2 ========
    const int wn_s = warp * 16;
    const uint32_t bn_s = (uint32_t)((wn_s + frow) * 128);
    const uint32_t am_s = (uint32_t)(frow * 128);

    // phase 3: M=16, in INT3 @16K ch2K, out INT4 @24K ch1K (all 16 rows valid)
    {
        float ac[2][4];
#pragma unroll
        for (int b = 0; b < 2; ++b)
#pragma unroll
            for (int c = 0; c < 4; ++c) ac[b][c] = 0.f;
#pragma unroll
        for (int kc = 0; kc < 4; ++kc) {
            const uint32_t Ab = sb + 16384u + (uint32_t)kc * 2048u;
            const uint32_t Bb = sb + FB_OFF + (uint32_t)kc * 16384u;
#pragma unroll
            for (int ks = 0; ks < 4; ++ks) {
                uint32_t af[4], bf[4];
                ldsm4(Ab + am_s + ko[ks], af);
                ldsm4(Bb + bn_s + ko[ks], bf);
#pragma unroll
                for (int ni = 0; ni < 2; ++ni)
                    mma_f16(ac[ni], af, bf[ni], bf[2 + ni]);
            }
        }
#pragma unroll
        for (int ni = 0; ni < 2; ++ni) {
            int col = wn_s + ni * 8 + 2 * tg;
            emit_h(24576u, 1024u, q,     col, ac[ni][0], ac[ni][1]);
            emit_h(24576u, 1024u, q + 8, col, ac[ni][2], ac[ni][3]);
        }
        __syncthreads();
    }
    // phase 4: M=8, in INT4 @24K ch1K, out INT5 @0 ch512 (rows q valid)
    {
        float ac[2][4];
#pragma unroll
        for (int b = 0; b < 2; ++b)
#pragma unroll
            for (int c = 0; c < 4; ++c) ac[b][c] = 0.f;
#pragma unroll
        for (int kc = 0; kc < 4; ++kc) {
            const uint32_t Ab = sb + 24576u + (uint32_t)kc * 1024u;
            const uint32_t Bb = sb + FB_OFF + (uint32_t)kc * 16384u;
#pragma unroll
            for (int ks = 0; ks < 4; ++ks) {
                uint32_t af[4], bf[4];
                ldsm4(Ab + am_s + ko[ks], af);
                ldsm4(Bb + bn_s + ko[ks], bf);
#pragma unroll
                for (int ni = 0; ni < 2; ++ni)
                    mma_f16(ac[ni], af, bf[ni], bf[2 + ni]);
            }
        }
#pragma unroll
        for (int ni = 0; ni < 2; ++ni) {
            int col = wn_s + ni * 8 + 2 * tg;
            emit_h(0u, 512u, q, col, ac[ni][0], ac[ni][1]);
        }
        __syncthreads();
    }
    // phase 5: M=4, in INT5 @0 ch512, out INT6 @4K ch256 (rows q<4 valid)
    {
        float ac[2][4];
#pragma unroll
        for (int b = 0; b < 2; ++b)
#pragma unroll
            for (int c = 0; c < 4; ++c) ac[b][c] = 0.f;
#pragma unroll
        for (int kc = 0; kc < 4; ++kc) {
            const uint32_t Ab = sb + (uint32_t)kc * 512u;
            const uint32_t Bb = sb + FB_OFF + (uint32_t)kc * 16384u;
#pragma unroll
            for (int ks = 0; ks < 4; ++ks) {
                uint32_t af[4], bf[4];
                ldsm4(Ab + am_s + ko[ks], af);
                ldsm4(Bb + bn_s + ko[ks], bf);
#pragma unroll
                for (int ni = 0; ni < 2; ++ni)
                    mma_f16(ac[ni], af, bf[ni], bf[2 + ni]);
            }
        }
        if (q < 4) {
#pragma unroll
            for (int ni = 0; ni < 2; ++ni) {
                int col = wn_s + ni * 8 + 2 * tg;
                emit_h(4096u, 256u, q, col, ac[ni][0], ac[ni][1]);
            }
        }
        __syncthreads();
    }
    // phase 6: M=2, in INT6 @4K ch256, out roots fp32 @8K (rows q<2 valid)
    float* roots = (float*)(smem + 8192);
    {
        float ac[2][4];
#pragma unroll
        for (int b = 0; b < 2; ++b)
#pragma unroll
            for (int c = 0; c < 4; ++c) ac[b][c] = 0.f;
#pragma unroll
        for (int kc = 0; kc < 4; ++kc) {
            const uint32_t Ab = sb + 4096u + (uint32_t)kc * 256u;
            const uint32_t Bb = sb + FB_OFF + (uint32_t)kc * 16384u;
#pragma unroll
            for (int ks = 0; ks < 4; ++ks) {
                uint32_t af[4], bf[4];
                ldsm4(Ab + am_s + ko[ks], af);
                ldsm4(Bb + bn_s + ko[ks], bf);
#pragma unroll
                for (int ni = 0; ni < 2; ++ni)
                    mma_f16(ac[ni], af, bf[ni], bf[2 + ni]);
            }
        }
        if (q < 2) {
#pragma unroll
            for (int ni = 0; ni < 2; ++ni) {
                int col = wn_s + ni * 8 + 2 * tg;
                float2 v;
                v.x = tanh_fast(ac[ni][0] + bias_s[col]);
                v.y = tanh_fast(ac[ni][1] + bias_s[col + 1]);
                *(float2*)(roots + q * 128 + col) = v;
            }
        }
        __syncthreads();
    }

    // ================= classifier: 2 roots -> out3 ============================
    if (warp < 2) {
        float4 rv = ((const float4*)(roots + warp * 128))[lane];
        float s[3];
#pragma unroll
        for (int o = 0; o < 3; ++o) {
            float4 wv = __ldg((const float4*)(Wc + o * 128) + lane);
            s[o] = rv.x * wv.x + rv.y * wv.y + rv.z * wv.z + rv.w * wv.w;
        }
#pragma unroll
        for (int off = 16; off; off >>= 1)
#pragma unroll
            for (int o = 0; o < 3; ++o) s[o] += __shfl_xor_sync(~0u, s[o], off);
        if (lane < 3) out3[(blockIdx.x * 2 + warp) * 3 + lane] = s[lane] + __ldg(&bc[lane]);
    }
}

// ---------------- launch ----------------
extern "C" void kernel_launch(void* const* d_in, const int* in_sizes, int n_in,
                              void* d_out, int out_size)
{
    const void*  tokens = d_in[0];
    const float* emb    = (const float*)d_in[1];
    const float* W_tree = (const float*)d_in[2];
    const float* b_tree = (const float*)d_in[3];
    const float* W_cls  = (const float*)d_in[4];
    const float* b_cls  = (const float*)d_in[5];
    float* out = (float*)d_out;

    cudaFuncSetAttribute(tree_mono,
                         cudaFuncAttributeMaxDynamicSharedMemorySize, F_SMEM);

    prep_all<<<2048, 256>>>(emb, W_tree, (const int*)tokens);
    tree_mono<<<2048, 256, F_SMEM>>>(tokens, b_tree, W_cls, b_cls, out);
}